// round 3
// baseline (speedup 1.0000x reference)
#include <cuda_runtime.h>
#include <cuda_bf16.h>
#include <cstdint>

// ===================== problem constants =====================
#define BDIM 8192
#define DDIM 512
#define BM 256
#define BN 128
#define BK 64          // bf16 per K-chunk = 128 bytes/row (one SW128 atom row)
#define NK (DDIM / BK) // 8
#define NSTAGE 4

#define A_STAGE_BYTES (BM * 128)                     // 32 KB
#define B_STAGE_BYTES (BN * 128)                     // 16 KB
#define SMEM_STAGE_BYTES (A_STAGE_BYTES + B_STAGE_BYTES)  // 48 KB
#define SMEM_BYTES (NSTAGE * SMEM_STAGE_BYTES)       // 192 KB

// ===================== device scratch =====================
__device__ __nv_bfloat16 g_vn[(size_t)BDIM * DDIM];
__device__ __nv_bfloat16 g_tn[(size_t)BDIM * DDIM];
__device__ float g_sum;

// ===================== helpers =====================
__device__ __forceinline__ uint32_t smem_u32(const void* p) {
    uint32_t a;
    asm("{ .reg .u64 t; cvta.to.shared.u64 t, %1; cvt.u32.u64 %0, t; }" : "=r"(a) : "l"(p));
    return a;
}

#define SWZ128(off) ((off) ^ (((off) >> 3) & 0x70))

__device__ __forceinline__ void cp_async16(uint32_t saddr, const void* gptr) {
    asm volatile("cp.async.cg.shared.global [%0], [%1], 16;\n" :: "r"(saddr), "l"(gptr) : "memory");
}
__device__ __forceinline__ void cp_commit() {
    asm volatile("cp.async.commit_group;\n" ::: "memory");
}
template <int N>
__device__ __forceinline__ void cp_wait() {
    asm volatile("cp.async.wait_group %0;\n" :: "n"(N) : "memory");
}

__device__ __forceinline__ void ldsm_x4(uint32_t& r0, uint32_t& r1, uint32_t& r2, uint32_t& r3,
                                        uint32_t addr) {
    asm volatile("ldmatrix.sync.aligned.m8n8.x4.shared.b16 {%0,%1,%2,%3}, [%4];"
                 : "=r"(r0), "=r"(r1), "=r"(r2), "=r"(r3) : "r"(addr));
}

__device__ __forceinline__ void mma16816(float* d, const uint32_t* a, const uint32_t* b) {
    asm volatile(
        "mma.sync.aligned.m16n8k16.row.col.f32.bf16.bf16.f32 "
        "{%0,%1,%2,%3}, {%4,%5,%6,%7}, {%8,%9}, {%0,%1,%2,%3};"
        : "+f"(d[0]), "+f"(d[1]), "+f"(d[2]), "+f"(d[3])
        : "r"(a[0]), "r"(a[1]), "r"(a[2]), "r"(a[3]), "r"(b[0]), "r"(b[1]));
}

// ===================== kernel A: L2-normalize rows (warp per row) =====================
__global__ void __launch_bounds__(256) norm_kernel(const float* __restrict__ v,
                                                   const float* __restrict__ t) {
    int wid = threadIdx.x >> 5, lane = threadIdx.x & 31;
    int row = blockIdx.x * 8 + wid;   // 2048 blocks * 8 warps = 16384 rows
    const float* src;
    __nv_bfloat16* dst;
    if (row < BDIM) {
        src = v + (size_t)row * DDIM;
        dst = g_vn + (size_t)row * DDIM;
    } else {
        int r2 = row - BDIM;
        src = t + (size_t)r2 * DDIM;
        dst = g_tn + (size_t)r2 * DDIM;
    }
    float4 a[4];
    float ss = 0.0f;
#pragma unroll
    for (int i = 0; i < 4; i++) {
        a[i] = reinterpret_cast<const float4*>(src)[lane + i * 32];
        ss += a[i].x * a[i].x + a[i].y * a[i].y + a[i].z * a[i].z + a[i].w * a[i].w;
    }
#pragma unroll
    for (int o = 16; o; o >>= 1) ss += __shfl_xor_sync(0xffffffffu, ss, o);
    float sc = 1.0f / fmaxf(sqrtf(ss), 1e-12f);
#pragma unroll
    for (int i = 0; i < 4; i++) {
        __nv_bfloat162 lo = __floats2bfloat162_rn(a[i].x * sc, a[i].y * sc);
        __nv_bfloat162 hi = __floats2bfloat162_rn(a[i].z * sc, a[i].w * sc);
        uint2 pk = make_uint2(*(uint32_t*)&lo, *(uint32_t*)&hi);
        reinterpret_cast<uint2*>(dst)[lane + i * 32] = pk;
    }
    if (blockIdx.x == 0 && threadIdx.x == 0) g_sum = 0.0f;
}

// ===================== kernel B: mma.sync GEMM + fused BCE =====================
__device__ __forceinline__ void load_chunk(const __nv_bfloat16* Ag, const __nv_bfloat16* Bg,
                                           int kk, uint32_t stageBase, int tid) {
    const __nv_bfloat16* gA = Ag + kk * BK;
    const __nv_bfloat16* gB = Bg + kk * BK;
#pragma unroll
    for (int i = 0; i < 8; i++) {               // A: 256 rows x 8 segs = 2048 16B chunks
        int c = tid + i * 256;
        int row = c >> 3, seg = c & 7;
        uint32_t off = (uint32_t)(row * 128 + seg * 16);
        cp_async16(stageBase + SWZ128(off), gA + (size_t)row * DDIM + seg * 8);
    }
#pragma unroll
    for (int i = 0; i < 4; i++) {               // B: 128 rows x 8 segs = 1024 16B chunks
        int c = tid + i * 256;
        int row = c >> 3, seg = c & 7;
        uint32_t off = (uint32_t)(row * 128 + seg * 16);
        cp_async16(stageBase + A_STAGE_BYTES + SWZ128(off), gB + (size_t)row * DDIM + seg * 8);
    }
    cp_commit();
}

__global__ void __launch_bounds__(256, 1) gemm_bce_kernel(const float* __restrict__ log_temp,
                                                          const float* __restrict__ bias) {
    extern __shared__ char smem[];
    uint32_t sbase = smem_u32(smem);
    int tid = threadIdx.x;
    int wid = tid >> 5, lane = tid & 31;
    int warp_m = wid >> 1, warp_n = wid & 1;   // 4 x 2 warp grid: 64 rows x 64 cols each

    int tm = blockIdx.y, tn = blockIdx.x;
    const __nv_bfloat16* Ag = g_vn + (size_t)tm * BM * DDIM;
    const __nv_bfloat16* Bg = g_tn + (size_t)tn * BN * DDIM;

    float acc[4][8][4];
#pragma unroll
    for (int i = 0; i < 4; i++)
#pragma unroll
        for (int j = 0; j < 8; j++)
#pragma unroll
            for (int e = 0; e < 4; e++) acc[i][j][e] = 0.0f;

    // Precomputed swizzled ldmatrix base addresses (XOR ks*32 per k-step) — verified R2 layout.
    uint32_t aC[4];
#pragma unroll
    for (int mt = 0; mt < 4; mt++) {
        int row = warp_m * 64 + mt * 16 + (lane & 15);
        uint32_t m = (uint32_t)((row & 7) * 16);
        uint32_t hi = (uint32_t)((lane >> 4) * 16);
        aC[mt] = (uint32_t)(row * 128) + ((hi ^ m) & 0x10u) + (m & 0x60u);
    }
    uint32_t bC[4];
#pragma unroll
    for (int np = 0; np < 4; np++) {
        int n = warp_n * 64 + np * 16 + (lane & 7) + ((lane >> 4) * 8);
        uint32_t m = (uint32_t)((n & 7) * 16);
        uint32_t hi = (uint32_t)(((lane >> 3) & 1) * 16);
        bC[np] = (uint32_t)(n * 128) + ((hi ^ m) & 0x10u) + (m & 0x60u) + (uint32_t)A_STAGE_BYTES;
    }

    // prologue: prefetch chunks 0,1,2
    load_chunk(Ag, Bg, 0, sbase + 0 * SMEM_STAGE_BYTES, tid);
    load_chunk(Ag, Bg, 1, sbase + 1 * SMEM_STAGE_BYTES, tid);
    load_chunk(Ag, Bg, 2, sbase + 2 * SMEM_STAGE_BYTES, tid);

    int s = 0, ps = 3;
#pragma unroll 1
    for (int k = 0; k < NK; k++) {
        if (k + 1 < NK) cp_wait<2>(); else cp_wait<0>();
        __syncthreads();

        // issue prefetch for k+3 BEFORE compute (its slot was consumed at chunk k-1)
        if (k + 3 < NK)
            load_chunk(Ag, Bg, k + 3, sbase + (uint32_t)ps * SMEM_STAGE_BYTES, tid);

        uint32_t stage = sbase + (uint32_t)s * SMEM_STAGE_BYTES;
#pragma unroll
        for (int ks = 0; ks < 4; ks++) {
            uint32_t kx = (uint32_t)(ks * 32);
            uint32_t a[4][4];
#pragma unroll
            for (int mt = 0; mt < 4; mt++)
                ldsm_x4(a[mt][0], a[mt][1], a[mt][2], a[mt][3], stage + (aC[mt] ^ kx));
#pragma unroll
            for (int np = 0; np < 4; np++) {
                uint32_t b[4];
                ldsm_x4(b[0], b[1], b[2], b[3], stage + (bC[np] ^ kx));
#pragma unroll
                for (int mt = 0; mt < 4; mt++) {
                    mma16816(acc[mt][np * 2 + 0], a[mt], &b[0]);
                    mma16816(acc[mt][np * 2 + 1], a[mt], &b[2]);
                }
            }
        }

        s = (s == NSTAGE - 1) ? 0 : s + 1;
        ps = (ps == NSTAGE - 1) ? 0 : ps + 1;
    }

    // -------- fused BCE epilogue --------
    float inv_temp = 1.0f / __expf(*log_temp);
    float bval = *bias;
    float lsum = 0.0f;
    int row0 = tm * BM + warp_m * 64 + (lane >> 2);
    int col0 = tn * BN + warp_n * 64 + (lane & 3) * 2;

#pragma unroll
    for (int mt = 0; mt < 4; mt++) {
#pragma unroll
        for (int nt = 0; nt < 8; nt++) {
#pragma unroll
            for (int e = 0; e < 4; e++) {
                float sim = acc[mt][nt][e];
                float z = fminf(fmaxf(fmaf(sim, inv_temp, bval), -30.0f), 30.0f);
                float x = __expf(-fabsf(z));
                // log1p(x), x small here: 3-term series
                float p = x * (1.0f - x * (0.5f - 0.33333333f * x));
                float bce = fmaxf(z, 0.0f) + p;
                int row = row0 + mt * 16 + (e >> 1) * 8;
                int col = col0 + nt * 8 + (e & 1);
                if (row == col) bce -= z;   // diagonal positive label
                lsum += bce;
            }
        }
    }
#pragma unroll
    for (int o = 16; o; o >>= 1) lsum += __shfl_xor_sync(0xffffffffu, lsum, o);

    // block reduction -> single atomicAdd per CTA
    float* red = reinterpret_cast<float*>(smem);
    __syncthreads();               // pipeline smem fully consumed; reuse
    if (lane == 0) red[wid] = lsum;
    __syncthreads();
    if (tid == 0) {
        float sblk = 0.0f;
#pragma unroll
        for (int i = 0; i < 8; i++) sblk += red[i];
        atomicAdd(&g_sum, sblk);
    }
}

// ===================== kernel C: finalize =====================
__global__ void finalize_kernel(float* out) {
    out[0] = g_sum * (1.0f / ((float)BDIM * (float)BDIM));
}

// ===================== launch =====================
extern "C" void kernel_launch(void* const* d_in, const int* in_sizes, int n_in,
                              void* d_out, int out_size) {
    const float* v = (const float*)d_in[0];
    const float* t = (const float*)d_in[1];
    const float* log_temp = (const float*)d_in[2];
    const float* bias = (const float*)d_in[3];
    float* out = (float*)d_out;

    norm_kernel<<<2 * BDIM / 8, 256>>>(v, t);

    cudaFuncSetAttribute(gemm_bce_kernel, cudaFuncAttributeMaxDynamicSharedMemorySize, SMEM_BYTES);
    dim3 grid(BDIM / BN, BDIM / BM);
    gemm_bce_kernel<<<grid, 256, SMEM_BYTES>>>(log_temp, bias);

    finalize_kernel<<<1, 1>>>(out);
}

// round 4
// speedup vs baseline: 1.1580x; 1.1580x over previous
#include <cuda_runtime.h>
#include <cuda_bf16.h>
#include <cstdint>

// ===================== problem constants =====================
#define BDIM 8192
#define DDIM 512
#define BM 128
#define BN 128
#define BK 64          // bf16 per K-chunk = 128 bytes/row (one SW128 atom row)
#define NK (DDIM / BK) // 8
#define NSTAGE 3

#define SMEM_STAGE_BYTES (2 * BM * 128)              // A 16KB + B 16KB = 32KB
#define SMEM_BYTES (NSTAGE * SMEM_STAGE_BYTES)       // 98304

// ===================== device scratch =====================
__device__ __nv_bfloat16 g_vn[(size_t)BDIM * DDIM];
__device__ __nv_bfloat16 g_tn[(size_t)BDIM * DDIM];
__device__ float g_sum;

// ===================== helpers =====================
__device__ __forceinline__ uint32_t smem_u32(const void* p) {
    uint32_t a;
    asm("{ .reg .u64 t; cvta.to.shared.u64 t, %1; cvt.u32.u64 %0, t; }" : "=r"(a) : "l"(p));
    return a;
}

#define SWZ128(off) ((off) ^ (((off) >> 3) & 0x70))

__device__ __forceinline__ void cp_async16(uint32_t saddr, const void* gptr) {
    asm volatile("cp.async.cg.shared.global [%0], [%1], 16;\n" :: "r"(saddr), "l"(gptr) : "memory");
}
__device__ __forceinline__ void cp_commit() {
    asm volatile("cp.async.commit_group;\n" ::: "memory");
}
template <int N>
__device__ __forceinline__ void cp_wait() {
    asm volatile("cp.async.wait_group %0;\n" :: "n"(N) : "memory");
}

__device__ __forceinline__ void ldsm_x4(uint32_t& r0, uint32_t& r1, uint32_t& r2, uint32_t& r3,
                                        uint32_t addr) {
    asm volatile("ldmatrix.sync.aligned.m8n8.x4.shared.b16 {%0,%1,%2,%3}, [%4];"
                 : "=r"(r0), "=r"(r1), "=r"(r2), "=r"(r3) : "r"(addr));
}

__device__ __forceinline__ void mma16816(float* d, const uint32_t* a, const uint32_t* b) {
    asm volatile(
        "mma.sync.aligned.m16n8k16.row.col.f32.bf16.bf16.f32 "
        "{%0,%1,%2,%3}, {%4,%5,%6,%7}, {%8,%9}, {%0,%1,%2,%3};"
        : "+f"(d[0]), "+f"(d[1]), "+f"(d[2]), "+f"(d[3])
        : "r"(a[0]), "r"(a[1]), "r"(a[2]), "r"(a[3]), "r"(b[0]), "r"(b[1]));
}

// ===================== kernel A: L2-normalize rows (warp per row) =====================
__global__ void __launch_bounds__(256) norm_kernel(const float* __restrict__ v,
                                                   const float* __restrict__ t) {
    int wid = threadIdx.x >> 5, lane = threadIdx.x & 31;
    int row = blockIdx.x * 8 + wid;   // 2048 blocks * 8 warps = 16384 rows
    const float* src;
    __nv_bfloat16* dst;
    if (row < BDIM) {
        src = v + (size_t)row * DDIM;
        dst = g_vn + (size_t)row * DDIM;
    } else {
        int r2 = row - BDIM;
        src = t + (size_t)r2 * DDIM;
        dst = g_tn + (size_t)r2 * DDIM;
    }
    float4 a[4];
    float ss = 0.0f;
#pragma unroll
    for (int i = 0; i < 4; i++) {
        a[i] = reinterpret_cast<const float4*>(src)[lane + i * 32];
        ss += a[i].x * a[i].x + a[i].y * a[i].y + a[i].z * a[i].z + a[i].w * a[i].w;
    }
#pragma unroll
    for (int o = 16; o; o >>= 1) ss += __shfl_xor_sync(0xffffffffu, ss, o);
    float sc = 1.0f / fmaxf(sqrtf(ss), 1e-12f);
#pragma unroll
    for (int i = 0; i < 4; i++) {
        __nv_bfloat162 lo = __floats2bfloat162_rn(a[i].x * sc, a[i].y * sc);
        __nv_bfloat162 hi = __floats2bfloat162_rn(a[i].z * sc, a[i].w * sc);
        uint2 pk = make_uint2(*(uint32_t*)&lo, *(uint32_t*)&hi);
        reinterpret_cast<uint2*>(dst)[lane + i * 32] = pk;
    }
    if (blockIdx.x == 0 && threadIdx.x == 0) g_sum = 0.0f;
}

// ===================== kernel B: mma.sync GEMM + fused BCE =====================
__device__ __forceinline__ void load_chunk(const __nv_bfloat16* Ag, const __nv_bfloat16* Bg,
                                           int kk, uint32_t stageBase, int tid) {
    const __nv_bfloat16* gA = Ag + kk * BK;
    const __nv_bfloat16* gB = Bg + kk * BK;
#pragma unroll
    for (int i = 0; i < 4; i++) {
        int c = tid + i * 256;          // 1024 16B-chunks : 128 rows x 8 segs
        int row = c >> 3, seg = c & 7;
        uint32_t off = (uint32_t)(row * 128 + seg * 16);
        cp_async16(stageBase + SWZ128(off), gA + (size_t)row * DDIM + seg * 8);
    }
#pragma unroll
    for (int i = 0; i < 4; i++) {
        int c = tid + i * 256;
        int row = c >> 3, seg = c & 7;
        uint32_t off = (uint32_t)(row * 128 + seg * 16);
        cp_async16(stageBase + 16384 + SWZ128(off), gB + (size_t)row * DDIM + seg * 8);
    }
    cp_commit();
}

__global__ void __launch_bounds__(256, 2) gemm_bce_kernel(const float* __restrict__ log_temp,
                                                          const float* __restrict__ bias) {
    extern __shared__ char smem[];
    uint32_t sbase = smem_u32(smem);
    int tid = threadIdx.x;
    int wid = tid >> 5, lane = tid & 31;
    int warp_m = wid >> 1, warp_n = wid & 1;   // 4 x 2 warp grid: 32 rows x 64 cols each

    int tm = blockIdx.y, tn = blockIdx.x;
    const __nv_bfloat16* Ag = g_vn + (size_t)tm * BM * DDIM;
    const __nv_bfloat16* Bg = g_tn + (size_t)tn * BN * DDIM;

    float acc[2][8][4];
#pragma unroll
    for (int i = 0; i < 2; i++)
#pragma unroll
        for (int j = 0; j < 8; j++)
#pragma unroll
            for (int e = 0; e < 4; e++) acc[i][j][e] = 0.0f;

    // Precomputed swizzled ldmatrix base addresses (XOR ks*32 per k-step) — verified layout.
    uint32_t aC[2];
#pragma unroll
    for (int mt = 0; mt < 2; mt++) {
        int row = warp_m * 32 + mt * 16 + (lane & 15);
        uint32_t m = (uint32_t)((row & 7) * 16);
        uint32_t hi = (uint32_t)((lane >> 4) * 16);
        aC[mt] = (uint32_t)(row * 128) + ((hi ^ m) & 0x10u) + (m & 0x60u);
    }
    uint32_t bC[4];
#pragma unroll
    for (int np = 0; np < 4; np++) {
        int n = warp_n * 64 + np * 16 + (lane & 7) + ((lane >> 4) * 8);
        uint32_t m = (uint32_t)((n & 7) * 16);
        uint32_t hi = (uint32_t)(((lane >> 3) & 1) * 16);
        bC[np] = (uint32_t)(n * 128) + ((hi ^ m) & 0x10u) + (m & 0x60u) + 16384u;
    }

    // prologue: prefetch chunks 0,1
    load_chunk(Ag, Bg, 0, sbase + 0 * SMEM_STAGE_BYTES, tid);
    load_chunk(Ag, Bg, 1, sbase + 1 * SMEM_STAGE_BYTES, tid);

    int s = 0, ps = 2;
#pragma unroll 1
    for (int k = 0; k < NK; k++) {
        if (k + 1 < NK) cp_wait<1>(); else cp_wait<0>();
        __syncthreads();

        // issue prefetch for k+2 BEFORE compute so its L2 latency hides under HMMAs
        if (k + 2 < NK)
            load_chunk(Ag, Bg, k + 2, sbase + (uint32_t)ps * SMEM_STAGE_BYTES, tid);

        uint32_t stage = sbase + (uint32_t)s * SMEM_STAGE_BYTES;
#pragma unroll
        for (int ks = 0; ks < 4; ks++) {
            uint32_t kx = (uint32_t)(ks * 32);
            uint32_t a[2][4];
#pragma unroll
            for (int mt = 0; mt < 2; mt++)
                ldsm_x4(a[mt][0], a[mt][1], a[mt][2], a[mt][3], stage + (aC[mt] ^ kx));
#pragma unroll
            for (int np = 0; np < 4; np++) {
                uint32_t b[4];
                ldsm_x4(b[0], b[1], b[2], b[3], stage + (bC[np] ^ kx));
#pragma unroll
                for (int mt = 0; mt < 2; mt++) {
                    mma16816(acc[mt][np * 2 + 0], a[mt], &b[0]);
                    mma16816(acc[mt][np * 2 + 1], a[mt], &b[2]);
                }
            }
        }

        s = (s == NSTAGE - 1) ? 0 : s + 1;
        ps = (ps == NSTAGE - 1) ? 0 : ps + 1;
    }

    // -------- fused BCE epilogue --------
    float inv_temp = 1.0f / __expf(*log_temp);
    float bval = *bias;
    float lsum = 0.0f;
    int row0 = tm * BM + warp_m * 32 + (lane >> 2);
    int col0 = tn * BN + warp_n * 64 + (lane & 3) * 2;

#pragma unroll
    for (int mt = 0; mt < 2; mt++) {
#pragma unroll
        for (int nt = 0; nt < 8; nt++) {
#pragma unroll
            for (int e = 0; e < 4; e++) {
                float sim = acc[mt][nt][e];
                float z = fminf(fmaxf(fmaf(sim, inv_temp, bval), -30.0f), 30.0f);
                float x = __expf(-fabsf(z));
                // log1p(x), x small here: 3-term series
                float p = x * (1.0f - x * (0.5f - 0.33333333f * x));
                float bce = fmaxf(z, 0.0f) + p;
                int row = row0 + mt * 16 + (e >> 1) * 8;
                int col = col0 + nt * 8 + (e & 1);
                if (row == col) bce -= z;   // diagonal positive label
                lsum += bce;
            }
        }
    }
#pragma unroll
    for (int o = 16; o; o >>= 1) lsum += __shfl_xor_sync(0xffffffffu, lsum, o);

    // block reduction -> single atomicAdd per CTA (pipeline smem is dead now)
    float* red = reinterpret_cast<float*>(smem);
    __syncthreads();
    if (lane == 0) red[wid] = lsum;
    __syncthreads();
    if (tid == 0) {
        float sblk = 0.0f;
#pragma unroll
        for (int i = 0; i < 8; i++) sblk += red[i];
        atomicAdd(&g_sum, sblk);
    }
}

// ===================== kernel C: finalize =====================
__global__ void finalize_kernel(float* out) {
    out[0] = g_sum * (1.0f / ((float)BDIM * (float)BDIM));
}

// ===================== launch =====================
extern "C" void kernel_launch(void* const* d_in, const int* in_sizes, int n_in,
                              void* d_out, int out_size) {
    const float* v = (const float*)d_in[0];
    const float* t = (const float*)d_in[1];
    const float* log_temp = (const float*)d_in[2];
    const float* bias = (const float*)d_in[3];
    float* out = (float*)d_out;

    norm_kernel<<<2 * BDIM / 8, 256>>>(v, t);

    cudaFuncSetAttribute(gemm_bce_kernel, cudaFuncAttributeMaxDynamicSharedMemorySize, SMEM_BYTES);
    dim3 grid(BDIM / BN, BDIM / BM);
    gemm_bce_kernel<<<grid, 256, SMEM_BYTES>>>(log_temp, bias);

    finalize_kernel<<<1, 1>>>(out);
}